// round 13
// baseline (speedup 1.0000x reference)
#include <cuda_runtime.h>
#include <cuda_bf16.h>
#include <cuda_fp16.h>
#include <cstdint>

// Problem constants
#define B_    256
#define T_    512
#define EMB_  512
#define HID_  1024
#define HEAD_ 100
#define NCLS_ 10
#define VOC_  32000
#define BH    (B_*HID_)

#define MTILES 250            // vocab tiles (m)
#define NTILES 8              // hidden column tiles (n)
#define NGEMM  (MTILES*NTILES)
#define NREC   128            // rec CTAs appended after GEMM CTAs

// ---------------- static device scratch -------------------------------------
__device__ __half g_projh[(size_t)VOC_*HID_];   // emb @ U^T in fp16, 66 MB
__device__ __half g_Ah[(size_t)VOC_*EMB_];      // emb fp16 (rounded once)
__device__ __half g_Bh[HID_*EMB_];              // U fp16 (rounded once)
__device__ float  g_h [BH];
__device__ float  g_h2[BH];
__device__ float  g_wdiag[HID_];
__device__ int    g_flag;
__device__ unsigned g_barcnt;
__device__ unsigned g_cnt[NTILES];              // per-column-tile completion count

// ---------------- init / diagonal check (vectorized) ------------------------
__global__ void k_init() {
    g_flag = 1; g_barcnt = 0u;
    for (int i = 0; i < NTILES; i++) g_cnt[i] = 0u;
}

__global__ void k_check(const float* __restrict__ W) {
    const int row = blockIdx.x;                 // 1024 blocks, 256 threads
    const int j4  = threadIdx.x;
    float4 v = __ldg(reinterpret_cast<const float4*>(W + (size_t)row * HID_) + j4);
    float vv[4] = {v.x, v.y, v.z, v.w};
#pragma unroll
    for (int p = 0; p < 4; p++) {
        int col = j4 * 4 + p;
        if (col == row)           g_wdiag[row] = vv[p];
        else if (vv[p] != 0.0f)   g_flag = 0;
    }
}

// ---------------- fp32 -> fp16 round ----------------------------------------
__global__ void k_split1(const float* __restrict__ src, __half* __restrict__ hi, int n4) {
    int i = blockIdx.x * blockDim.x + threadIdx.x;
    if (i >= n4) return;
    float4 v = __ldg(reinterpret_cast<const float4*>(src) + i);
    float vv[4] = {v.x, v.y, v.z, v.w};
    __half h[4];
#pragma unroll
    for (int p = 0; p < 4; p++) h[p] = __float2half_rn(vv[p]);
    *reinterpret_cast<uint2*>(hi + 4*(size_t)i) =
        make_uint2((unsigned)__half_as_ushort(h[0]) | ((unsigned)__half_as_ushort(h[1]) << 16),
                   (unsigned)__half_as_ushort(h[2]) | ((unsigned)__half_as_ushort(h[3]) << 16));
}

// ---------------- mma/ldsm/cp.async helpers ----------------------------------
__device__ __forceinline__ void ldsm4(unsigned& r0, unsigned& r1,
                                      unsigned& r2, unsigned& r3, unsigned addr) {
    asm volatile("ldmatrix.sync.aligned.m8n8.x4.shared.b16 {%0,%1,%2,%3},[%4];\n"
                 : "=r"(r0), "=r"(r1), "=r"(r2), "=r"(r3) : "r"(addr));
}
__device__ __forceinline__ void mma_f16(float* c, const unsigned* a, const unsigned* b) {
    asm volatile(
        "mma.sync.aligned.m16n8k16.row.col.f32.f16.f16.f32 "
        "{%0,%1,%2,%3},{%4,%5,%6,%7},{%8,%9},{%0,%1,%2,%3};\n"
        : "+f"(c[0]), "+f"(c[1]), "+f"(c[2]), "+f"(c[3])
        : "r"(a[0]), "r"(a[1]), "r"(a[2]), "r"(a[3]), "r"(b[0]), "r"(b[1]));
}
__device__ __forceinline__ void cp16(unsigned dst, const void* src) {
    asm volatile("cp.async.cg.shared.global [%0], [%1], 16;\n" :: "r"(dst), "l"(src) : "memory");
}
__device__ __forceinline__ void cp_commit() {
    asm volatile("cp.async.commit_group;\n" ::: "memory");
}
template<int N> __device__ __forceinline__ void cp_wait() {
    asm volatile("cp.async.wait_group %0;\n" :: "n"(N) : "memory");
}

// GEMM geometry: CTA 128x128, 8 warps (2m x 4n), warp 64x32,
// BK=64 (four k16 subs per stage), 2-stage double buffer, occ 2.
#define SMS 24                                   // smem row stride in fp16 elems
#define SUB_BYTES (128*SMS*2)                    // 6144 B per tensor per k16 sub
#define STG_BYTES (8*SUB_BYTES)                  // A0..A3,B0..B3 = 49152 B
#define NSTG 2
#define SMEM_TOTAL (NSTG*STG_BYTES)              // 98304 B; x2 CTAs = 192 KB/SM
#define NIT (EMB_/64)                            // 8 stages

// Fused kernel: bid < NGEMM -> GEMM CTA (m-fast raster, signals column tile);
//               bid >= NGEMM -> recurrence CTA (waits for its column tile).
__global__ void __launch_bounds__(256, 2)
k_fused(const __half* __restrict__ Ahg, const __half* __restrict__ Bhg,
        const int* __restrict__ ids, const float* __restrict__ Wb) {
    extern __shared__ __align__(16) char smem_dyn[];
    const int bid = blockIdx.x;
    const int tid = threadIdx.x;

    if (bid < NGEMM) {
        // ================= GEMM part =================
        const unsigned sb = (unsigned)__cvta_generic_to_shared(smem_dyn);
        const int mt = bid % MTILES, nt = bid / MTILES;   // m-fast raster
        const int m0 = mt * 128, n0 = nt * 128;
        const int r = tid >> 1, q = tid & 1;
        const unsigned doff = (unsigned)(r * SMS + q * 8) * 2;

        const __half* a_h = Ahg + (size_t)(m0 + r) * EMB_ + q * 8;
        const __half* b_h = Bhg + (size_t)(n0 + r) * EMB_ + q * 8;

        const int lane = tid & 31, warp = tid >> 5;
        const int wm = warp >> 2, wn = warp & 3;

        float acc[4][4][4];
#pragma unroll
        for (int i = 0; i < 4; i++)
#pragma unroll
            for (int j = 0; j < 4; j++)
#pragma unroll
                for (int k = 0; k < 4; k++) acc[i][j][k] = 0.0f;

        auto load_stage = [&](int s, int c) {
            unsigned base = sb + s * STG_BYTES + doff;
            const int k0 = c * 64;
#pragma unroll
            for (int sub = 0; sub < 4; ++sub) {
                cp16(base + sub * SUB_BYTES,       a_h + k0 + sub * 16);
                cp16(base + (4 + sub) * SUB_BYTES, b_h + k0 + sub * 16);
            }
            cp_commit();
        };

        load_stage(0, 0);
        load_stage(1, 1);

        const int aoff0 = ((wm * 64 + (lane & 15)) * SMS + (lane >> 4) * 8) * 2;
        const int boff0 = ((wn * 32 + (lane & 7) + ((lane >> 4) << 3)) * SMS
                           + ((lane >> 3) & 1) * 8) * 2;

        for (int it = 0; it < NIT; ++it) {
            if (it < NIT-1) cp_wait<1>(); else cp_wait<0>();
            __syncthreads();

            const unsigned stg = sb + (it & 1) * STG_BYTES;
#pragma unroll
            for (int sub = 0; sub < 4; ++sub) {
                const unsigned abase = stg + sub * SUB_BYTES;
                const unsigned bbase = stg + (4 + sub) * SUB_BYTES;
                unsigned Ah[4][4], Bh[4][2];
#pragma unroll
                for (int mi = 0; mi < 4; mi++) {
                    unsigned ad = abase + aoff0 + mi * 16 * SMS * 2;
                    ldsm4(Ah[mi][0], Ah[mi][1], Ah[mi][2], Ah[mi][3], ad);
                }
#pragma unroll
                for (int p = 0; p < 2; p++) {
                    unsigned bd = bbase + boff0 + p * 16 * SMS * 2;
                    ldsm4(Bh[2*p][0], Bh[2*p][1], Bh[2*p+1][0], Bh[2*p+1][1], bd);
                }
#pragma unroll
                for (int mi = 0; mi < 4; mi++)
#pragma unroll
                    for (int ni = 0; ni < 4; ni++)
                        mma_f16(acc[mi][ni], Ah[mi], Bh[ni]);
            }

            __syncthreads();
            if (it + 2 < NIT) load_stage(it & 1, it + 2);
        }

        // epilogue: fp32 accumulators -> fp16 g_projh
#pragma unroll
        for (int mi = 0; mi < 4; mi++) {
            int mrow = m0 + wm * 64 + mi * 16 + (lane >> 2);
#pragma unroll
            for (int ni = 0; ni < 4; ni++) {
                int h = n0 + wn * 32 + ni * 8 + (lane & 3) * 2;
                *reinterpret_cast<__half2*>(&g_projh[(size_t)mrow * HID_ + h]) =
                    __floats2half2_rn(acc[mi][ni][0], acc[mi][ni][1]);
                *reinterpret_cast<__half2*>(&g_projh[(size_t)(mrow + 8) * HID_ + h]) =
                    __floats2half2_rn(acc[mi][ni][2], acc[mi][ni][3]);
            }
        }

        // signal column tile completion
        __threadfence();
        __syncthreads();
        if (tid == 0) atomicAdd(&g_cnt[nt], 1u);

    } else {
        // ================= recurrence part (diagonal fast path) =================
        if (!g_flag) return;
        const int rb  = bid - NGEMM;            // 0..127
        const int nt  = rb >> 4;                 // column tile 0..7
        const int sub = rb & 15;
        const int b   = sub * 16 + (tid >> 4);   // batch 0..255
        const int h8  = nt * 128 + (tid & 15) * 8;

        // wait for column tile nt to be fully written
        if (tid == 0) {
            while (atomicAdd(&g_cnt[nt], 0u) < (unsigned)MTILES) {}
            __threadfence();
        }
        __syncthreads();

        float w[8], bb[8], hv[8];
#pragma unroll
        for (int p = 0; p < 8; p++) {
            w[p]  = g_wdiag[h8 + p];
            bb[p] = __ldg(&Wb[h8 + p]);
            hv[p] = 0.0f;
        }
        const int* idrow = ids + b * T_;
#pragma unroll 4
        for (int t = 0; t < T_; ++t) {
            int id = __ldg(&idrow[t]);
            uint4 raw = *reinterpret_cast<const uint4*>(&g_projh[(size_t)id * HID_ + h8]);
            unsigned rr[4] = {raw.x, raw.y, raw.z, raw.w};
#pragma unroll
            for (int p = 0; p < 4; p++) {
                float2 ux = __half22float2(*reinterpret_cast<const __half2*>(&rr[p]));
                hv[2*p]   = fmaxf(fmaf(hv[2*p],   w[2*p],   bb[2*p]   + ux.x), 0.f);
                hv[2*p+1] = fmaxf(fmaf(hv[2*p+1], w[2*p+1], bb[2*p+1] + ux.y), 0.f);
            }
        }
        float4* dst = reinterpret_cast<float4*>(&g_h[((size_t)b << 10) + h8]);
        dst[0] = make_float4(hv[0], hv[1], hv[2], hv[3]);
        dst[1] = make_float4(hv[4], hv[5], hv[6], hv[7]);
    }
}

// ---------------- recurrence, generic fallback (dormant in practice) --------
__global__ void k_rec_fb(const int* __restrict__ ids,
                         const float* __restrict__ W, const float* __restrict__ Wb) {
    if (g_flag) return;
    const int tid = blockIdx.x * blockDim.x + threadIdx.x;
    const int NT = gridDim.x * blockDim.x;
    for (int t = 0; t < T_; ++t) {
        const float* cur = (t & 1) ? g_h2 : g_h;
        float*       nxt = (t & 1) ? g_h  : g_h2;
        for (int o = tid; o < BH; o += NT) {
            int b = o >> 10, i = o & 1023;
            int id = ids[b * T_ + t];
            float s = Wb[i] + __half2float(g_projh[(size_t)id * HID_ + i]);
            if (t > 0) {
                const float* hr = cur + (b << 10);
                const float* wr = W + ((size_t)i << 10);
                for (int j = 0; j < HID_; ++j) s += hr[j] * wr[j];
            }
            nxt[o] = fmaxf(s, 0.0f);
        }
        __syncthreads();
        if (threadIdx.x == 0) {
            __threadfence();
            atomicAdd(&g_barcnt, 1u);
            while (atomicAdd(&g_barcnt, 0u) < 148u * (unsigned)(t + 1)) {}
        }
        __syncthreads();
    }
}

// ---------------- head ------------------------------------------------------
__global__ void k_head(const float* __restrict__ h1w, const float* __restrict__ h1b,
                       const float* __restrict__ h2w, const float* __restrict__ h2b,
                       float* __restrict__ out) {
    __shared__ float hs[HID_];
    __shared__ float zs[HEAD_];
    const int b = blockIdx.x, tid = threadIdx.x;
    const float* hrow = g_h + (size_t)b * HID_;
    for (int k = tid; k < HID_; k += 128) hs[k] = hrow[k];
    __syncthreads();

    const int warp = tid >> 5, lane = tid & 31;
    for (int j = warp; j < HEAD_; j += 4) {
        float s = 0.0f;
        const float* w = h1w + (size_t)j * HID_;
        for (int k = lane; k < HID_; k += 32) s += hs[k] * w[k];
#pragma unroll
        for (int o = 16; o; o >>= 1) s += __shfl_xor_sync(0xffffffffu, s, o);
        if (lane == 0) zs[j] = fmaxf(s + h1b[j], 0.0f);
    }
    __syncthreads();

    for (int c = warp; c < NCLS_; c += 4) {
        float s = 0.0f;
        const float* w = h2w + (size_t)c * HEAD_;
        for (int j = lane; j < HEAD_; j += 32) s += zs[j] * w[j];
#pragma unroll
        for (int o = 16; o; o >>= 1) s += __shfl_xor_sync(0xffffffffu, s, o);
        if (lane == 0) out[b * NCLS_ + c] = s + h2b[c];
    }
}

// ---------------- launcher ---------------------------------------------------
extern "C" void kernel_launch(void* const* d_in, const int* in_sizes, int n_in,
                              void* d_out, int out_size) {
    const int*   ids = (const int*)  d_in[0];
    const float* emb = (const float*)d_in[1];
    const float* U   = (const float*)d_in[2];
    const float* W   = (const float*)d_in[3];
    const float* Wb  = (const float*)d_in[4];
    const float* h1w = (const float*)d_in[5];
    const float* h1b = (const float*)d_in[6];
    const float* h2w = (const float*)d_in[7];
    const float* h2b = (const float*)d_in[8];
    float* out = (float*)d_out;

    cudaFuncSetAttribute(k_fused, cudaFuncAttributeMaxDynamicSharedMemorySize, SMEM_TOTAL);

    __half *ah, *bh;
    cudaGetSymbolAddress((void**)&ah, g_Ah);
    cudaGetSymbolAddress((void**)&bh, g_Bh);

    k_init<<<1, 1>>>();
    k_check<<<HID_, 256>>>(W);
    k_split1<<<(VOC_*EMB_/4 + 255)/256, 256>>>(emb, ah, VOC_*EMB_/4);
    k_split1<<<(HID_*EMB_/4 + 255)/256, 256>>>(U, bh, HID_*EMB_/4);
    k_fused<<<NGEMM + NREC, 256, SMEM_TOTAL>>>(ah, bh, ids, Wb);
    k_rec_fb<<<148, 256>>>(ids, W, Wb);
    k_head<<<B_, 128>>>(h1w, h1b, h2w, h2b, out);
}

// round 14
// speedup vs baseline: 1.0903x; 1.0903x over previous
#include <cuda_runtime.h>
#include <cuda_bf16.h>
#include <cuda_fp16.h>
#include <cstdint>

// Problem constants
#define B_    256
#define T_    512
#define EMB_  512
#define HID_  1024
#define HEAD_ 100
#define NCLS_ 10
#define VOC_  32000
#define BH    (B_*HID_)

#define MTILES 250            // vocab tiles (m)
#define NTILES 8              // hidden column tiles (n)
#define NGEMM  (MTILES*NTILES)
#define NREC   128            // rec CTAs appended after GEMM CTAs

// ---------------- static device scratch -------------------------------------
__device__ __half g_projh[(size_t)VOC_*HID_];   // emb @ U^T in fp16, 66 MB
__device__ __half g_Ah[(size_t)VOC_*EMB_];      // emb fp16 (rounded once)
__device__ __half g_Bh[HID_*EMB_];              // U fp16 (rounded once)
__device__ float  g_h [BH];
__device__ float  g_h2[BH];
__device__ float  g_wdiag[HID_];
__device__ int    g_flag;
__device__ unsigned g_barcnt;
__device__ unsigned g_cnt[NTILES];              // per-column-tile completion count

// ---------------- init / diagonal check (vectorized) ------------------------
__global__ void k_init() {
    g_flag = 1; g_barcnt = 0u;
    for (int i = 0; i < NTILES; i++) g_cnt[i] = 0u;
}

__global__ void k_check(const float* __restrict__ W) {
    const int row = blockIdx.x;                 // 1024 blocks, 256 threads
    const int j4  = threadIdx.x;
    float4 v = __ldg(reinterpret_cast<const float4*>(W + (size_t)row * HID_) + j4);
    float vv[4] = {v.x, v.y, v.z, v.w};
#pragma unroll
    for (int p = 0; p < 4; p++) {
        int col = j4 * 4 + p;
        if (col == row)           g_wdiag[row] = vv[p];
        else if (vv[p] != 0.0f)   g_flag = 0;
    }
}

// ---------------- fp32 -> fp16 round ----------------------------------------
__global__ void k_split1(const float* __restrict__ src, __half* __restrict__ hi, int n4) {
    int i = blockIdx.x * blockDim.x + threadIdx.x;
    if (i >= n4) return;
    float4 v = __ldg(reinterpret_cast<const float4*>(src) + i);
    float vv[4] = {v.x, v.y, v.z, v.w};
    __half h[4];
#pragma unroll
    for (int p = 0; p < 4; p++) h[p] = __float2half_rn(vv[p]);
    *reinterpret_cast<uint2*>(hi + 4*(size_t)i) =
        make_uint2((unsigned)__half_as_ushort(h[0]) | ((unsigned)__half_as_ushort(h[1]) << 16),
                   (unsigned)__half_as_ushort(h[2]) | ((unsigned)__half_as_ushort(h[3]) << 16));
}

// ---------------- mma/ldsm/cp.async helpers ----------------------------------
__device__ __forceinline__ void ldsm4(unsigned& r0, unsigned& r1,
                                      unsigned& r2, unsigned& r3, unsigned addr) {
    asm volatile("ldmatrix.sync.aligned.m8n8.x4.shared.b16 {%0,%1,%2,%3},[%4];\n"
                 : "=r"(r0), "=r"(r1), "=r"(r2), "=r"(r3) : "r"(addr));
}
__device__ __forceinline__ void mma_f16(float* c, const unsigned* a, const unsigned* b) {
    asm volatile(
        "mma.sync.aligned.m16n8k16.row.col.f32.f16.f16.f32 "
        "{%0,%1,%2,%3},{%4,%5,%6,%7},{%8,%9},{%0,%1,%2,%3};\n"
        : "+f"(c[0]), "+f"(c[1]), "+f"(c[2]), "+f"(c[3])
        : "r"(a[0]), "r"(a[1]), "r"(a[2]), "r"(a[3]), "r"(b[0]), "r"(b[1]));
}
__device__ __forceinline__ void cp16(unsigned dst, const void* src) {
    asm volatile("cp.async.cg.shared.global [%0], [%1], 16;\n" :: "r"(dst), "l"(src) : "memory");
}
__device__ __forceinline__ void cp_commit() {
    asm volatile("cp.async.commit_group;\n" ::: "memory");
}
template<int N> __device__ __forceinline__ void cp_wait() {
    asm volatile("cp.async.wait_group %0;\n" :: "n"(N) : "memory");
}

// GEMM geometry (R12 base): CTA 128x128, 8 warps (2m x 4n), warp 64x32,
// BK=32 (two k16 subs), 3-stage cp.async pipeline, occ 2.
// This round: fragment loads for BOTH subs hoisted, 32 contiguous MMAs.
#define SMS 24                                   // smem row stride in fp16 elems
#define SUB_BYTES (128*SMS*2)                    // 6144 B per tensor per k16 sub
#define STG_BYTES (4*SUB_BYTES)                  // A0,A1,B0,B1 = 24576 B
#define NSTG 3
#define SMEM_TOTAL (NSTG*STG_BYTES)              // 73728 B; x2 CTAs = 144 KB/SM
#define NIT (EMB_/32)                            // 16 stages

// Fused kernel: bid < NGEMM -> GEMM CTA (m-fast raster, signals column tile);
//               bid >= NGEMM -> recurrence CTA (waits for its column tile).
__global__ void __launch_bounds__(256, 2)
k_fused(const __half* __restrict__ Ahg, const __half* __restrict__ Bhg,
        const int* __restrict__ ids, const float* __restrict__ Wb) {
    extern __shared__ __align__(16) char smem_dyn[];
    const int bid = blockIdx.x;
    const int tid = threadIdx.x;

    if (bid < NGEMM) {
        // ================= GEMM part =================
        const unsigned sb = (unsigned)__cvta_generic_to_shared(smem_dyn);
        const int mt = bid % MTILES, nt = bid / MTILES;   // m-fast raster
        const int m0 = mt * 128, n0 = nt * 128;
        const int r = tid >> 1, q = tid & 1;
        const unsigned doff = (unsigned)(r * SMS + q * 8) * 2;

        const __half* a_h = Ahg + (size_t)(m0 + r) * EMB_ + q * 8;
        const __half* b_h = Bhg + (size_t)(n0 + r) * EMB_ + q * 8;

        const int lane = tid & 31, warp = tid >> 5;
        const int wm = warp >> 2, wn = warp & 3;

        float acc[4][4][4];
#pragma unroll
        for (int i = 0; i < 4; i++)
#pragma unroll
            for (int j = 0; j < 4; j++)
#pragma unroll
                for (int k = 0; k < 4; k++) acc[i][j][k] = 0.0f;

        auto load_stage = [&](int s, int c) {
            unsigned base = sb + s * STG_BYTES + doff;
            const int k0 = c * 32;
            cp16(base,               a_h + k0);
            cp16(base + 1*SUB_BYTES, a_h + k0 + 16);
            cp16(base + 2*SUB_BYTES, b_h + k0);
            cp16(base + 3*SUB_BYTES, b_h + k0 + 16);
            cp_commit();
        };

        load_stage(0, 0);
        load_stage(1, 1);

        const int aoff0 = ((wm * 64 + (lane & 15)) * SMS + (lane >> 4) * 8) * 2;
        const int boff0 = ((wn * 32 + (lane & 7) + ((lane >> 4) << 3)) * SMS
                           + ((lane >> 3) & 1) * 8) * 2;

        for (int it = 0; it < NIT; ++it) {
            if (it < NIT-1) cp_wait<1>(); else cp_wait<0>();
            __syncthreads();
            if (it + 2 < NIT) load_stage((it + 2) % NSTG, it + 2);

            const unsigned stg = sb + (it % NSTG) * STG_BYTES;
            unsigned Ah[2][4][4], Bh[2][4][2];
            // ---- hoisted fragment loads: 12 ldsm4 for both k16 subs ----
#pragma unroll
            for (int sub = 0; sub < 2; ++sub) {
                const unsigned abase = stg + sub * SUB_BYTES;
                const unsigned bbase = stg + (2 + sub) * SUB_BYTES;
#pragma unroll
                for (int mi = 0; mi < 4; mi++) {
                    unsigned ad = abase + aoff0 + mi * 16 * SMS * 2;
                    ldsm4(Ah[sub][mi][0], Ah[sub][mi][1], Ah[sub][mi][2], Ah[sub][mi][3], ad);
                }
#pragma unroll
                for (int p = 0; p < 2; p++) {
                    unsigned bd = bbase + boff0 + p * 16 * SMS * 2;
                    ldsm4(Bh[sub][2*p][0], Bh[sub][2*p][1],
                          Bh[sub][2*p+1][0], Bh[sub][2*p+1][1], bd);
                }
            }
            // ---- 32 contiguous MMAs (k order preserved per acc element) ----
#pragma unroll
            for (int sub = 0; sub < 2; ++sub)
#pragma unroll
                for (int mi = 0; mi < 4; mi++)
#pragma unroll
                    for (int ni = 0; ni < 4; ni++)
                        mma_f16(acc[mi][ni], Ah[sub][mi], Bh[sub][ni]);
        }

        // epilogue: fp32 accumulators -> fp16 g_projh
#pragma unroll
        for (int mi = 0; mi < 4; mi++) {
            int mrow = m0 + wm * 64 + mi * 16 + (lane >> 2);
#pragma unroll
            for (int ni = 0; ni < 4; ni++) {
                int h = n0 + wn * 32 + ni * 8 + (lane & 3) * 2;
                *reinterpret_cast<__half2*>(&g_projh[(size_t)mrow * HID_ + h]) =
                    __floats2half2_rn(acc[mi][ni][0], acc[mi][ni][1]);
                *reinterpret_cast<__half2*>(&g_projh[(size_t)(mrow + 8) * HID_ + h]) =
                    __floats2half2_rn(acc[mi][ni][2], acc[mi][ni][3]);
            }
        }

        // signal column tile completion
        __threadfence();
        __syncthreads();
        if (tid == 0) atomicAdd(&g_cnt[nt], 1u);

    } else {
        // ================= recurrence part (diagonal fast path) =================
        if (!g_flag) return;
        const int rb  = bid - NGEMM;            // 0..127
        const int nt  = rb >> 4;                 // column tile 0..7
        const int sub = rb & 15;
        const int b   = sub * 16 + (tid >> 4);   // batch 0..255
        const int h8  = nt * 128 + (tid & 15) * 8;

        // wait for column tile nt to be fully written
        if (tid == 0) {
            while (atomicAdd(&g_cnt[nt], 0u) < (unsigned)MTILES) {}
            __threadfence();
        }
        __syncthreads();

        float w[8], bb[8], hv[8];
#pragma unroll
        for (int p = 0; p < 8; p++) {
            w[p]  = g_wdiag[h8 + p];
            bb[p] = __ldg(&Wb[h8 + p]);
            hv[p] = 0.0f;
        }
        const int* idrow = ids + b * T_;
#pragma unroll 4
        for (int t = 0; t < T_; ++t) {
            int id = __ldg(&idrow[t]);
            uint4 raw = *reinterpret_cast<const uint4*>(&g_projh[(size_t)id * HID_ + h8]);
            unsigned rr[4] = {raw.x, raw.y, raw.z, raw.w};
#pragma unroll
            for (int p = 0; p < 4; p++) {
                float2 ux = __half22float2(*reinterpret_cast<const __half2*>(&rr[p]));
                hv[2*p]   = fmaxf(fmaf(hv[2*p],   w[2*p],   bb[2*p]   + ux.x), 0.f);
                hv[2*p+1] = fmaxf(fmaf(hv[2*p+1], w[2*p+1], bb[2*p+1] + ux.y), 0.f);
            }
        }
        float4* dst = reinterpret_cast<float4*>(&g_h[((size_t)b << 10) + h8]);
        dst[0] = make_float4(hv[0], hv[1], hv[2], hv[3]);
        dst[1] = make_float4(hv[4], hv[5], hv[6], hv[7]);
    }
}

// ---------------- recurrence, generic fallback (dormant in practice) --------
__global__ void k_rec_fb(const int* __restrict__ ids,
                         const float* __restrict__ W, const float* __restrict__ Wb) {
    if (g_flag) return;
    const int tid = blockIdx.x * blockDim.x + threadIdx.x;
    const int NT = gridDim.x * blockDim.x;
    for (int t = 0; t < T_; ++t) {
        const float* cur = (t & 1) ? g_h2 : g_h;
        float*       nxt = (t & 1) ? g_h  : g_h2;
        for (int o = tid; o < BH; o += NT) {
            int b = o >> 10, i = o & 1023;
            int id = ids[b * T_ + t];
            float s = Wb[i] + __half2float(g_projh[(size_t)id * HID_ + i]);
            if (t > 0) {
                const float* hr = cur + (b << 10);
                const float* wr = W + ((size_t)i << 10);
                for (int j = 0; j < HID_; ++j) s += hr[j] * wr[j];
            }
            nxt[o] = fmaxf(s, 0.0f);
        }
        __syncthreads();
        if (threadIdx.x == 0) {
            __threadfence();
            atomicAdd(&g_barcnt, 1u);
            while (atomicAdd(&g_barcnt, 0u) < 148u * (unsigned)(t + 1)) {}
        }
        __syncthreads();
    }
}

// ---------------- head ------------------------------------------------------
__global__ void k_head(const float* __restrict__ h1w, const float* __restrict__ h1b,
                       const float* __restrict__ h2w, const float* __restrict__ h2b,
                       float* __restrict__ out) {
    __shared__ float hs[HID_];
    __shared__ float zs[HEAD_];
    const int b = blockIdx.x, tid = threadIdx.x;
    const float* hrow = g_h + (size_t)b * HID_;
    for (int k = tid; k < HID_; k += 128) hs[k] = hrow[k];
    __syncthreads();

    const int warp = tid >> 5, lane = tid & 31;
    for (int j = warp; j < HEAD_; j += 4) {
        float s = 0.0f;
        const float* w = h1w + (size_t)j * HID_;
        for (int k = lane; k < HID_; k += 32) s += hs[k] * w[k];
#pragma unroll
        for (int o = 16; o; o >>= 1) s += __shfl_xor_sync(0xffffffffu, s, o);
        if (lane == 0) zs[j] = fmaxf(s + h1b[j], 0.0f);
    }
    __syncthreads();

    for (int c = warp; c < NCLS_; c += 4) {
        float s = 0.0f;
        const float* w = h2w + (size_t)c * HEAD_;
        for (int j = lane; j < HEAD_; j += 32) s += zs[j] * w[j];
#pragma unroll
        for (int o = 16; o; o >>= 1) s += __shfl_xor_sync(0xffffffffu, s, o);
        if (lane == 0) out[b * NCLS_ + c] = s + h2b[c];
    }
}

// ---------------- launcher ---------------------------------------------------
extern "C" void kernel_launch(void* const* d_in, const int* in_sizes, int n_in,
                              void* d_out, int out_size) {
    const int*   ids = (const int*)  d_in[0];
    const float* emb = (const float*)d_in[1];
    const float* U   = (const float*)d_in[2];
    const float* W   = (const float*)d_in[3];
    const float* Wb  = (const float*)d_in[4];
    const float* h1w = (const float*)d_in[5];
    const float* h1b = (const float*)d_in[6];
    const float* h2w = (const float*)d_in[7];
    const float* h2b = (const float*)d_in[8];
    float* out = (float*)d_out;

    cudaFuncSetAttribute(k_fused, cudaFuncAttributeMaxDynamicSharedMemorySize, SMEM_TOTAL);

    __half *ah, *bh;
    cudaGetSymbolAddress((void**)&ah, g_Ah);
    cudaGetSymbolAddress((void**)&bh, g_Bh);

    k_init<<<1, 1>>>();
    k_check<<<HID_, 256>>>(W);
    k_split1<<<(VOC_*EMB_/4 + 255)/256, 256>>>(emb, ah, VOC_*EMB_/4);
    k_split1<<<(HID_*EMB_/4 + 255)/256, 256>>>(U, bh, HID_*EMB_/4);
    k_fused<<<NGEMM + NREC, 256, SMEM_TOTAL>>>(ah, bh, ids, Wb);
    k_rec_fb<<<148, 256>>>(ids, W, Wb);
    k_head<<<B_, 128>>>(h1w, h1b, h2w, h2b, out);
}

// round 15
// speedup vs baseline: 1.4587x; 1.3379x over previous
#include <cuda_runtime.h>
#include <cuda_bf16.h>
#include <cuda_fp16.h>
#include <cstdint>

// Problem constants
#define B_    256
#define T_    512
#define EMB_  512
#define HID_  1024
#define HEAD_ 100
#define NCLS_ 10
#define VOC_  32000
#define BH    (B_*HID_)

#define MTILES 250            // vocab tiles (m)
#define NTILES 8              // hidden column tiles (n)
#define NGEMM  (MTILES*NTILES)
#define NREC   128            // rec CTAs appended after GEMM CTAs

// ---------------- static device scratch -------------------------------------
__device__ __half g_projh[(size_t)VOC_*HID_];   // emb @ U^T in fp16, 66 MB
__device__ __half g_Ah[(size_t)VOC_*EMB_];      // emb fp16 (rounded once)
__device__ __half g_Bh[HID_*EMB_];              // U fp16 (rounded once)
__device__ float  g_h [BH];
__device__ float  g_h2[BH];
__device__ float  g_wdiag[HID_];
__device__ int    g_flag;
__device__ unsigned g_maxw_bits;                // max |wdiag| as positive-float bits
__device__ unsigned g_barcnt;
__device__ unsigned g_cnt[NTILES];              // per-column-tile completion count

// ---------------- init / diagonal check (vectorized) ------------------------
__global__ void k_init() {
    g_flag = 1; g_barcnt = 0u; g_maxw_bits = 0u;
    for (int i = 0; i < NTILES; i++) g_cnt[i] = 0u;
}

__global__ void k_check(const float* __restrict__ W) {
    const int row = blockIdx.x;                 // 1024 blocks, 256 threads
    const int j4  = threadIdx.x;
    float4 v = __ldg(reinterpret_cast<const float4*>(W + (size_t)row * HID_) + j4);
    float vv[4] = {v.x, v.y, v.z, v.w};
#pragma unroll
    for (int p = 0; p < 4; p++) {
        int col = j4 * 4 + p;
        if (col == row) {
            g_wdiag[row] = vv[p];
            atomicMax(&g_maxw_bits, (unsigned)__float_as_int(fabsf(vv[p])));
        } else if (vv[p] != 0.0f)  g_flag = 0;
    }
}

// ---------------- fp32 -> fp16 round (both tensors, one launch) --------------
__global__ void k_split(const float* __restrict__ emb, const float* __restrict__ U,
                        __half* __restrict__ ah, __half* __restrict__ bh) {
    const int nA = VOC_*EMB_/4;
    const int nT = nA + HID_*EMB_/4;
    int i = blockIdx.x * blockDim.x + threadIdx.x;
    if (i >= nT) return;
    const float4* src; __half* dst; int j;
    if (i < nA) { src = reinterpret_cast<const float4*>(emb); dst = ah; j = i; }
    else        { src = reinterpret_cast<const float4*>(U);   dst = bh; j = i - nA; }
    float4 v = __ldg(src + j);
    float vv[4] = {v.x, v.y, v.z, v.w};
    __half h[4];
#pragma unroll
    for (int p = 0; p < 4; p++) h[p] = __float2half_rn(vv[p]);
    *reinterpret_cast<uint2*>(dst + 4*(size_t)j) =
        make_uint2((unsigned)__half_as_ushort(h[0]) | ((unsigned)__half_as_ushort(h[1]) << 16),
                   (unsigned)__half_as_ushort(h[2]) | ((unsigned)__half_as_ushort(h[3]) << 16));
}

// ---------------- mma/ldsm/cp.async helpers ----------------------------------
__device__ __forceinline__ void ldsm4(unsigned& r0, unsigned& r1,
                                      unsigned& r2, unsigned& r3, unsigned addr) {
    asm volatile("ldmatrix.sync.aligned.m8n8.x4.shared.b16 {%0,%1,%2,%3},[%4];\n"
                 : "=r"(r0), "=r"(r1), "=r"(r2), "=r"(r3) : "r"(addr));
}
__device__ __forceinline__ void mma_f16(float* c, const unsigned* a, const unsigned* b) {
    asm volatile(
        "mma.sync.aligned.m16n8k16.row.col.f32.f16.f16.f32 "
        "{%0,%1,%2,%3},{%4,%5,%6,%7},{%8,%9},{%0,%1,%2,%3};\n"
        : "+f"(c[0]), "+f"(c[1]), "+f"(c[2]), "+f"(c[3])
        : "r"(a[0]), "r"(a[1]), "r"(a[2]), "r"(a[3]), "r"(b[0]), "r"(b[1]));
}
__device__ __forceinline__ void cp16(unsigned dst, const void* src) {
    asm volatile("cp.async.cg.shared.global [%0], [%1], 16;\n" :: "r"(dst), "l"(src) : "memory");
}
__device__ __forceinline__ void cp_commit() {
    asm volatile("cp.async.commit_group;\n" ::: "memory");
}
template<int N> __device__ __forceinline__ void cp_wait() {
    asm volatile("cp.async.wait_group %0;\n" :: "n"(N) : "memory");
}

// GEMM geometry (R12 best): CTA 128x128, 8 warps (2m x 4n), warp 64x32,
// BK=32 (two k16 subs), 3-stage cp.async pipeline, occ 2.
#define SMS 24                                   // smem row stride in fp16 elems
#define SUB_BYTES (128*SMS*2)                    // 6144 B per tensor per k16 sub
#define STG_BYTES (4*SUB_BYTES)                  // A0,A1,B0,B1 = 24576 B
#define NSTG 3
#define SMEM_TOTAL (NSTG*STG_BYTES)              // 73728 B; x2 CTAs = 144 KB/SM
#define NIT (EMB_/32)                            // 16 stages

// Fused kernel: bid < NGEMM -> GEMM CTA (m-fast raster, signals column tile);
//               bid >= NGEMM -> truncated recurrence CTA (waits for its tile).
__global__ void __launch_bounds__(256, 2)
k_fused(const __half* __restrict__ Ahg, const __half* __restrict__ Bhg,
        const int* __restrict__ ids, const float* __restrict__ Wb) {
    extern __shared__ __align__(16) char smem_dyn[];
    const int bid = blockIdx.x;
    const int tid = threadIdx.x;

    if (bid < NGEMM) {
        // ================= GEMM part =================
        const unsigned sb = (unsigned)__cvta_generic_to_shared(smem_dyn);
        const int mt = bid % MTILES, nt = bid / MTILES;   // m-fast raster
        const int m0 = mt * 128, n0 = nt * 128;
        const int r = tid >> 1, q = tid & 1;
        const unsigned doff = (unsigned)(r * SMS + q * 8) * 2;

        const __half* a_h = Ahg + (size_t)(m0 + r) * EMB_ + q * 8;
        const __half* b_h = Bhg + (size_t)(n0 + r) * EMB_ + q * 8;

        const int lane = tid & 31, warp = tid >> 5;
        const int wm = warp >> 2, wn = warp & 3;

        float acc[4][4][4];
#pragma unroll
        for (int i = 0; i < 4; i++)
#pragma unroll
            for (int j = 0; j < 4; j++)
#pragma unroll
                for (int k = 0; k < 4; k++) acc[i][j][k] = 0.0f;

        auto load_stage = [&](int s, int c) {
            unsigned base = sb + s * STG_BYTES + doff;
            const int k0 = c * 32;
            cp16(base,               a_h + k0);
            cp16(base + 1*SUB_BYTES, a_h + k0 + 16);
            cp16(base + 2*SUB_BYTES, b_h + k0);
            cp16(base + 3*SUB_BYTES, b_h + k0 + 16);
            cp_commit();
        };

        load_stage(0, 0);
        load_stage(1, 1);

        const int aoff0 = ((wm * 64 + (lane & 15)) * SMS + (lane >> 4) * 8) * 2;
        const int boff0 = ((wn * 32 + (lane & 7) + ((lane >> 4) << 3)) * SMS
                           + ((lane >> 3) & 1) * 8) * 2;

        for (int it = 0; it < NIT; ++it) {
            if (it < NIT-1) cp_wait<1>(); else cp_wait<0>();
            __syncthreads();
            if (it + 2 < NIT) load_stage((it + 2) % NSTG, it + 2);

            const unsigned stg = sb + (it % NSTG) * STG_BYTES;
#pragma unroll
            for (int sub = 0; sub < 2; ++sub) {
                const unsigned base = stg + sub * SUB_BYTES;
                unsigned Ah[4][4], Bh[4][2];
#pragma unroll
                for (int mi = 0; mi < 4; mi++) {
                    unsigned ad = base + aoff0 + mi * 16 * SMS * 2;
                    ldsm4(Ah[mi][0], Ah[mi][1], Ah[mi][2], Ah[mi][3], ad);
                }
#pragma unroll
                for (int p = 0; p < 2; p++) {
                    unsigned bd = base + 2*SUB_BYTES + boff0 + p * 16 * SMS * 2;
                    ldsm4(Bh[2*p][0], Bh[2*p][1], Bh[2*p+1][0], Bh[2*p+1][1], bd);
                }
#pragma unroll
                for (int mi = 0; mi < 4; mi++)
#pragma unroll
                    for (int ni = 0; ni < 4; ni++)
                        mma_f16(acc[mi][ni], Ah[mi], Bh[ni]);
            }
        }

        // epilogue: fp32 accumulators -> fp16 g_projh
#pragma unroll
        for (int mi = 0; mi < 4; mi++) {
            int mrow = m0 + wm * 64 + mi * 16 + (lane >> 2);
#pragma unroll
            for (int ni = 0; ni < 4; ni++) {
                int h = n0 + wn * 32 + ni * 8 + (lane & 3) * 2;
                *reinterpret_cast<__half2*>(&g_projh[(size_t)mrow * HID_ + h]) =
                    __floats2half2_rn(acc[mi][ni][0], acc[mi][ni][1]);
                *reinterpret_cast<__half2*>(&g_projh[(size_t)(mrow + 8) * HID_ + h]) =
                    __floats2half2_rn(acc[mi][ni][2], acc[mi][ni][3]);
            }
        }

        // signal column tile completion
        __threadfence();
        __syncthreads();
        if (tid == 0) atomicAdd(&g_cnt[nt], 1u);

    } else {
        // ========== truncated recurrence (diagonal fast path) ==========
        if (!g_flag) return;
        const int rb  = bid - NGEMM;            // 0..127
        const int nt  = rb >> 4;                 // column tile 0..7
        const int sub = rb & 15;
        const int b   = sub * 16 + (tid >> 4);   // batch 0..255
        const int h8  = nt * 128 + (tid & 15) * 8;

        // safe truncation horizon: influence of h_{T-K} on h_T <= max|w|^K.
        // pick smallest K with max|w|^K <= 2^-40 (K = T if max|w| ~>= 1).
        const float mw = __int_as_float((int)g_maxw_bits);
        int K = T_;
        if (mw < 0.999f) {
            float l2 = log2f(fmaxf(mw, 1e-30f));         // negative
            K = (int)ceilf(-40.0f / l2);
            if (K < 1) K = 1;
            if (K > T_) K = T_;
        }
        const int t0 = T_ - K;

        // wait for column tile nt to be fully written (gentle backoff)
        if (tid == 0) {
            while (atomicAdd(&g_cnt[nt], 0u) < (unsigned)MTILES) __nanosleep(200);
            __threadfence();
        }
        __syncthreads();

        float w[8], bb[8], hv[8];
#pragma unroll
        for (int p = 0; p < 8; p++) {
            w[p]  = g_wdiag[h8 + p];
            bb[p] = __ldg(&Wb[h8 + p]);
            hv[p] = 0.0f;
        }
        const int* idrow = ids + b * T_;
        for (int t = t0; t < T_; ++t) {
            int id = __ldg(&idrow[t]);
            uint4 raw = *reinterpret_cast<const uint4*>(&g_projh[(size_t)id * HID_ + h8]);
            unsigned rr[4] = {raw.x, raw.y, raw.z, raw.w};
#pragma unroll
            for (int p = 0; p < 4; p++) {
                float2 ux = __half22float2(*reinterpret_cast<const __half2*>(&rr[p]));
                hv[2*p]   = fmaxf(fmaf(hv[2*p],   w[2*p],   bb[2*p]   + ux.x), 0.f);
                hv[2*p+1] = fmaxf(fmaf(hv[2*p+1], w[2*p+1], bb[2*p+1] + ux.y), 0.f);
            }
        }
        float4* dst = reinterpret_cast<float4*>(&g_h[((size_t)b << 10) + h8]);
        dst[0] = make_float4(hv[0], hv[1], hv[2], hv[3]);
        dst[1] = make_float4(hv[4], hv[5], hv[6], hv[7]);
    }
}

// ---------------- recurrence, generic fallback (dormant in practice) --------
__global__ void k_rec_fb(const int* __restrict__ ids,
                         const float* __restrict__ W, const float* __restrict__ Wb) {
    if (g_flag) return;
    const int tid = blockIdx.x * blockDim.x + threadIdx.x;
    const int NT = gridDim.x * blockDim.x;
    for (int t = 0; t < T_; ++t) {
        const float* cur = (t & 1) ? g_h2 : g_h;
        float*       nxt = (t & 1) ? g_h  : g_h2;
        for (int o = tid; o < BH; o += NT) {
            int b = o >> 10, i = o & 1023;
            int id = ids[b * T_ + t];
            float s = Wb[i] + __half2float(g_projh[(size_t)id * HID_ + i]);
            if (t > 0) {
                const float* hr = cur + (b << 10);
                const float* wr = W + ((size_t)i << 10);
                for (int j = 0; j < HID_; ++j) s += hr[j] * wr[j];
            }
            nxt[o] = fmaxf(s, 0.0f);
        }
        __syncthreads();
        if (threadIdx.x == 0) {
            __threadfence();
            atomicAdd(&g_barcnt, 1u);
            while (atomicAdd(&g_barcnt, 0u) < 148u * (unsigned)(t + 1)) {}
        }
        __syncthreads();
    }
}

// ---------------- head ------------------------------------------------------
__global__ void k_head(const float* __restrict__ h1w, const float* __restrict__ h1b,
                       const float* __restrict__ h2w, const float* __restrict__ h2b,
                       float* __restrict__ out) {
    __shared__ float hs[HID_];
    __shared__ float zs[HEAD_];
    const int b = blockIdx.x, tid = threadIdx.x;
    const float* hrow = g_h + (size_t)b * HID_;
    for (int k = tid; k < HID_; k += 128) hs[k] = hrow[k];
    __syncthreads();

    const int warp = tid >> 5, lane = tid & 31;
    for (int j = warp; j < HEAD_; j += 4) {
        float s = 0.0f;
        const float* w = h1w + (size_t)j * HID_;
        for (int k = lane; k < HID_; k += 32) s += hs[k] * w[k];
#pragma unroll
        for (int o = 16; o; o >>= 1) s += __shfl_xor_sync(0xffffffffu, s, o);
        if (lane == 0) zs[j] = fmaxf(s + h1b[j], 0.0f);
    }
    __syncthreads();

    for (int c = warp; c < NCLS_; c += 4) {
        float s = 0.0f;
        const float* w = h2w + (size_t)c * HEAD_;
        for (int j = lane; j < HEAD_; j += 32) s += zs[j] * w[j];
#pragma unroll
        for (int o = 16; o; o >>= 1) s += __shfl_xor_sync(0xffffffffu, s, o);
        if (lane == 0) out[b * NCLS_ + c] = s + h2b[c];
    }
}

// ---------------- launcher ---------------------------------------------------
extern "C" void kernel_launch(void* const* d_in, const int* in_sizes, int n_in,
                              void* d_out, int out_size) {
    const int*   ids = (const int*)  d_in[0];
    const float* emb = (const float*)d_in[1];
    const float* U   = (const float*)d_in[2];
    const float* W   = (const float*)d_in[3];
    const float* Wb  = (const float*)d_in[4];
    const float* h1w = (const float*)d_in[5];
    const float* h1b = (const float*)d_in[6];
    const float* h2w = (const float*)d_in[7];
    const float* h2b = (const float*)d_in[8];
    float* out = (float*)d_out;

    cudaFuncSetAttribute(k_fused, cudaFuncAttributeMaxDynamicSharedMemorySize, SMEM_TOTAL);

    __half *ah, *bh;
    cudaGetSymbolAddress((void**)&ah, g_Ah);
    cudaGetSymbolAddress((void**)&bh, g_Bh);

    k_init<<<1, 1>>>();
    k_check<<<HID_, 256>>>(W);
    k_split<<<((VOC_+HID_)*EMB_/4 + 255)/256, 256>>>(emb, U, ah, bh);
    k_fused<<<NGEMM + NREC, 256, SMEM_TOTAL>>>(ah, bh, ids, Wb);
    k_rec_fb<<<148, 256>>>(ids, W, Wb);
    k_head<<<B_, 128>>>(h1w, h1b, h2w, h2b, out);
}